// round 7
// baseline (speedup 1.0000x reference)
#include <cuda_runtime.h>
#include <cuda_bf16.h>
#include <cstdint>
#include <math.h>

#define NB 32
#define NS 1024
#define NH 1024
#define ND 128

// persistent scratch (__device__ globals per allocation rules) — split bf16
__device__ __nv_bfloat16 g_xh[NB * NS * NH];
__device__ __nv_bfloat16 g_xl[NB * NS * NH];
__device__ __nv_bfloat16 g_qh[NB * NS * ND];
__device__ __nv_bfloat16 g_ql[NB * NS * ND];
__device__ __nv_bfloat16 g_kh[NB * NS * ND];
__device__ __nv_bfloat16 g_kl[NB * NS * ND];
__device__ __nv_bfloat16 g_vh[NB * NS * ND];
__device__ __nv_bfloat16 g_vl[NB * NS * ND];
__device__ __nv_bfloat16 g_ph[NB * NS * NS];   // split normalized probs
__device__ __nv_bfloat16 g_pl[NB * NS * NS];
__device__ __nv_bfloat16 g_wthi[3 * ND * NH];  // [w][n][k]
__device__ __nv_bfloat16 g_wtlo[3 * ND * NH];

// ---------------------------------------------------------------------------
// helpers
// ---------------------------------------------------------------------------
__device__ __forceinline__ uint32_t smem_u32(const void* p) {
    uint32_t a;
    asm("{ .reg .u64 t; cvta.to.shared.u64 t, %1; cvt.u32.u64 %0, t; }" : "=r"(a) : "l"(p));
    return a;
}
__device__ __forceinline__ void ldsm_x4(uint32_t* r, uint32_t addr) {
    asm volatile("ldmatrix.sync.aligned.m8n8.x4.shared.b16 {%0,%1,%2,%3}, [%4];"
                 : "=r"(r[0]), "=r"(r[1]), "=r"(r[2]), "=r"(r[3]) : "r"(addr));
}
__device__ __forceinline__ void ldsm_x4_t(uint32_t* r, uint32_t addr) {
    asm volatile("ldmatrix.sync.aligned.m8n8.x4.trans.shared.b16 {%0,%1,%2,%3}, [%4];"
                 : "=r"(r[0]), "=r"(r[1]), "=r"(r[2]), "=r"(r[3]) : "r"(addr));
}
__device__ __forceinline__ void mma16816(float* d, const uint32_t* a, const uint32_t* b) {
    asm volatile(
        "mma.sync.aligned.m16n8k16.row.col.f32.bf16.bf16.f32 "
        "{%0,%1,%2,%3}, {%4,%5,%6,%7}, {%8,%9}, {%0,%1,%2,%3};"
        : "+f"(d[0]), "+f"(d[1]), "+f"(d[2]), "+f"(d[3])
        : "r"(a[0]), "r"(a[1]), "r"(a[2]), "r"(a[3]), "r"(b[0]), "r"(b[1]));
}
__device__ __forceinline__ void split2(float a, float b, uint32_t& hi, uint32_t& lo) {
    __nv_bfloat16 ha = __float2bfloat16(a), hb = __float2bfloat16(b);
    __nv_bfloat16 la = __float2bfloat16(a - __bfloat162float(ha));
    __nv_bfloat16 lb = __float2bfloat16(b - __bfloat162float(hb));
    hi = (uint32_t)__bfloat16_as_ushort(ha) | ((uint32_t)__bfloat16_as_ushort(hb) << 16);
    lo = (uint32_t)__bfloat16_as_ushort(la) | ((uint32_t)__bfloat16_as_ushort(lb) << 16);
}
__device__ __forceinline__ float fast_exp(float x) {
    float t = x * 1.4426950408889634f;
    int ii = __float2int_rn(t);
    float f = t - (float)ii;
    float y = f * 0.6931471805599453f;
    float p = 1.0f + y * (1.0f + y * (0.5f + y * (0.16666667f + y * (0.041666668f + y * 0.008333334f))));
    return __int_as_float(__float_as_int(p) + (ii << 23));
}
__device__ __forceinline__ void cp_async16(uint32_t smem_addr, const void* gptr) {
    asm volatile("cp.async.cg.shared.global [%0], [%1], 16;" :: "r"(smem_addr), "l"(gptr));
}
#define CP_COMMIT() asm volatile("cp.async.commit_group;" ::: "memory")
#define CP_WAIT(n)  asm volatile("cp.async.wait_group %0;" :: "n"(n) : "memory")

// ---------------------------------------------------------------------------
// X split
// ---------------------------------------------------------------------------
__global__ __launch_bounds__(256) void convx_kernel(const float* __restrict__ X)
{
    const int total = NB * NS * NH / 4;
    for (int i = blockIdx.x * 256 + threadIdx.x; i < total; i += gridDim.x * 256) {
        float4 v = ((const float4*)X)[i];
        uint2 h, l;
        split2(v.x, v.y, h.x, l.x);
        split2(v.z, v.w, h.y, l.y);
        ((uint2*)g_xh)[i] = h;
        ((uint2*)g_xl)[i] = l;
    }
}

// ---------------------------------------------------------------------------
// Weight transpose+split
// ---------------------------------------------------------------------------
__global__ __launch_bounds__(256) void convw_kernel(
    const float* __restrict__ Wq, const float* __restrict__ Wk, const float* __restrict__ Wv)
{
    __shared__ float sW[64 * 129];
    int w = blockIdx.x >> 4;
    int k0 = (blockIdx.x & 15) * 64;
    const float* W = (w == 0) ? Wq : (w == 1) ? Wk : Wv;
    int tid = threadIdx.x;

    #pragma unroll
    for (int it = 0; it < 32; it++) {
        int f = tid + it * 256;
        int kk = f >> 7, n = f & 127;
        sW[kk * 129 + n] = W[(size_t)(k0 + kk) * ND + n];
    }
    __syncthreads();

    #pragma unroll
    for (int it = 0; it < 32; it++) {
        int f = tid + it * 256;
        int n = f >> 6, kk = f & 63;
        float x = sW[kk * 129 + n];
        __nv_bfloat16 hi = __float2bfloat16(x);
        __nv_bfloat16 lo = __float2bfloat16(x - __bfloat162float(hi));
        size_t di = (size_t)w * ND * NH + (size_t)n * NH + k0 + kk;
        g_wthi[di] = hi;
        g_wtlo[di] = lo;
    }
}

// ---------------------------------------------------------------------------
// QKV GEMM: 2-stage cp.async, BM=128 BN=128 BK=32, 2 CTAs/SM.
// Inner MMA order: term-major (hh x4, hl x4, lh x4) -> dep distance 4.
// ---------------------------------------------------------------------------
#define TSTRIDE 40
#define QK_AHI 0
#define QK_ALO 10240
#define QK_BHI 20480
#define QK_BLO 30720
#define QK_STAGE 40960
#define QK_SMEM (2 * QK_STAGE)

__global__ __launch_bounds__(256, 2) void qkv_mma_kernel(
    const float* __restrict__ bq, const float* __restrict__ bk, const float* __restrict__ bv)
{
    extern __shared__ char sm[];
    const uint32_t uS = smem_u32(sm);

    const int tid = threadIdx.x;
    const int wid = tid >> 5, lid = tid & 31;
    const int m0 = blockIdx.x * 128;
    const int w  = blockIdx.y;

    const __nv_bfloat16* Whi = g_wthi + (size_t)w * ND * NH;
    const __nv_bfloat16* Wlo = g_wtlo + (size_t)w * ND * NH;
    const float* bias = (w == 0) ? bq : (w == 1) ? bk : bv;
    __nv_bfloat16* outh = (w == 0) ? g_qh : (w == 1) ? g_kh : g_vh;
    __nv_bfloat16* outl = (w == 0) ? g_ql : (w == 1) ? g_kl : g_vl;
    const float oscale = (w == 0) ? 0.08838834764831845f : 1.0f;

    const int warpM = (wid >> 1) * 32;
    const int warpN = (wid & 1) * 64;

    const int a_row  = lid & 15;
    const int a_koff = (lid >> 4) * 8;
    const int bx_row  = (lid & 7) + (lid >> 4) * 8;
    const int bx_koff = ((lid >> 3) & 1) * 8;

    float acc[2][8][4];
    #pragma unroll
    for (int i = 0; i < 2; i++)
        #pragma unroll
        for (int j = 0; j < 8; j++)
            #pragma unroll
            for (int c = 0; c < 4; c++) acc[i][j][c] = 0.f;

    auto issue_stage = [&](int kc, int s) {
        const int k0 = kc * 32;
        const uint32_t base = uS + s * QK_STAGE;
        #pragma unroll
        for (int it = 0; it < 4; it++) {
            int f = tid + it * 256;
            int arr = f >> 9, g = f & 511;
            int row = g >> 2, u = g & 3;
            const __nv_bfloat16* src = (arr ? g_xl : g_xh) + (size_t)(m0 + row) * NH + k0 + u * 8;
            cp_async16(base + (arr ? QK_ALO : QK_AHI) + (uint32_t)(row * TSTRIDE + u * 8) * 2, src);
        }
        #pragma unroll
        for (int it = 0; it < 4; it++) {
            int f = tid + it * 256;
            int arr = f >> 9, g = f & 511;
            int row = g >> 2, u = g & 3;
            const __nv_bfloat16* src = (arr ? Wlo : Whi) + (size_t)row * NH + k0 + u * 8;
            cp_async16(base + (arr ? QK_BLO : QK_BHI) + (uint32_t)(row * TSTRIDE + u * 8) * 2, src);
        }
        CP_COMMIT();
    };

    issue_stage(0, 0);

    for (int kc = 0; kc < 32; kc++) {
        if (kc < 31) { issue_stage(kc + 1, (kc + 1) & 1); CP_WAIT(1); }
        else         { CP_WAIT(0); }
        __syncthreads();

        const uint32_t base = uS + (kc & 1) * QK_STAGE;
        #pragma unroll
        for (int ks = 0; ks < 2; ks++) {
            uint32_t ahi[2][4], alo[2][4];
            #pragma unroll
            for (int mi = 0; mi < 2; mi++) {
                uint32_t off = ((warpM + mi * 16 + a_row) * TSTRIDE + ks * 16 + a_koff) * 2;
                ldsm_x4(ahi[mi], base + QK_AHI + off);
                ldsm_x4(alo[mi], base + QK_ALO + off);
            }
            #pragma unroll
            for (int njp = 0; njp < 4; njp++) {
                uint32_t boff = ((warpN + njp * 16 + bx_row) * TSTRIDE + ks * 16 + bx_koff) * 2;
                uint32_t bh[4], bl[4];
                ldsm_x4(bh, base + QK_BHI + boff);
                ldsm_x4(bl, base + QK_BLO + boff);
                // term-major: 4 independent accs per term
                #pragma unroll
                for (int h = 0; h < 2; h++)
                    #pragma unroll
                    for (int mi = 0; mi < 2; mi++)
                        mma16816(acc[mi][njp * 2 + h], ahi[mi], &bh[h * 2]);
                #pragma unroll
                for (int h = 0; h < 2; h++)
                    #pragma unroll
                    for (int mi = 0; mi < 2; mi++)
                        mma16816(acc[mi][njp * 2 + h], ahi[mi], &bl[h * 2]);
                #pragma unroll
                for (int h = 0; h < 2; h++)
                    #pragma unroll
                    for (int mi = 0; mi < 2; mi++)
                        mma16816(acc[mi][njp * 2 + h], alo[mi], &bh[h * 2]);
            }
        }
        __syncthreads();
    }

    #pragma unroll
    for (int mi = 0; mi < 2; mi++) {
        #pragma unroll
        for (int nj = 0; nj < 8; nj++) {
            int r0 = m0 + warpM + mi * 16 + (lid >> 2);
            int c0 = warpN + nj * 8 + (lid & 3) * 2;
            float b0 = bias[c0], b1 = bias[c0 + 1];
            float v0 = (acc[mi][nj][0] + b0) * oscale;
            float v1 = (acc[mi][nj][1] + b1) * oscale;
            float v2 = (acc[mi][nj][2] + b0) * oscale;
            float v3 = (acc[mi][nj][3] + b1) * oscale;
            uint32_t h01, l01, h23, l23;
            split2(v0, v1, h01, l01);
            split2(v2, v3, h23, l23);
            *(uint32_t*)&outh[(size_t)r0 * ND + c0] = h01;
            *(uint32_t*)&outl[(size_t)r0 * ND + c0] = l01;
            *(uint32_t*)&outh[(size_t)(r0 + 8) * ND + c0] = h23;
            *(uint32_t*)&outl[(size_t)(r0 + 8) * ND + c0] = l23;
        }
    }
}

// ---------------------------------------------------------------------------
// score_kernel: raw S = q_scaled @ k^T -> probs buffer (fp32).
// ---------------------------------------------------------------------------
__global__ __launch_bounds__(256, 2) void score_kernel(float* __restrict__ probs)
{
    extern __shared__ char sm[];
    const uint32_t uS = smem_u32(sm);

    const int tid = threadIdx.x;
    const int wid = tid >> 5, lid = tid & 31;
    const int m0 = blockIdx.x * 128;
    const int n0 = blockIdx.y * 128;
    const int b  = blockIdx.z;
    const size_t qbase = (size_t)(b * NS + m0) * ND;
    const size_t kbase = (size_t)(b * NS + n0) * ND;

    const int warpM = (wid >> 1) * 32;
    const int warpN = (wid & 1) * 64;
    const int a_row  = lid & 15;
    const int a_koff = (lid >> 4) * 8;
    const int bx_row  = (lid & 7) + (lid >> 4) * 8;
    const int bx_koff = ((lid >> 3) & 1) * 8;

    float acc[2][8][4];
    #pragma unroll
    for (int i = 0; i < 2; i++)
        #pragma unroll
        for (int j = 0; j < 8; j++)
            #pragma unroll
            for (int c = 0; c < 4; c++) acc[i][j][c] = 0.f;

    auto issue_stage = [&](int kc, int s) {
        const int k0 = kc * 32;
        const uint32_t base = uS + s * QK_STAGE;
        #pragma unroll
        for (int it = 0; it < 4; it++) {
            int f = tid + it * 256;
            int arr = f >> 9, g = f & 511;
            int row = g >> 2, u = g & 3;
            const __nv_bfloat16* src = (arr ? g_ql : g_qh) + qbase + (size_t)row * ND + k0 + u * 8;
            cp_async16(base + (arr ? QK_ALO : QK_AHI) + (uint32_t)(row * TSTRIDE + u * 8) * 2, src);
        }
        #pragma unroll
        for (int it = 0; it < 4; it++) {
            int f = tid + it * 256;
            int arr = f >> 9, g = f & 511;
            int row = g >> 2, u = g & 3;
            const __nv_bfloat16* src = (arr ? g_kl : g_kh) + kbase + (size_t)row * ND + k0 + u * 8;
            cp_async16(base + (arr ? QK_BLO : QK_BHI) + (uint32_t)(row * TSTRIDE + u * 8) * 2, src);
        }
        CP_COMMIT();
    };

    issue_stage(0, 0);

    for (int kc = 0; kc < 4; kc++) {
        if (kc < 3) { issue_stage(kc + 1, (kc + 1) & 1); CP_WAIT(1); }
        else        { CP_WAIT(0); }
        __syncthreads();

        const uint32_t base = uS + (kc & 1) * QK_STAGE;
        #pragma unroll
        for (int ks = 0; ks < 2; ks++) {
            uint32_t ahi[2][4], alo[2][4];
            #pragma unroll
            for (int mi = 0; mi < 2; mi++) {
                uint32_t off = ((warpM + mi * 16 + a_row) * TSTRIDE + ks * 16 + a_koff) * 2;
                ldsm_x4(ahi[mi], base + QK_AHI + off);
                ldsm_x4(alo[mi], base + QK_ALO + off);
            }
            #pragma unroll
            for (int njp = 0; njp < 4; njp++) {
                uint32_t boff = ((warpN + njp * 16 + bx_row) * TSTRIDE + ks * 16 + bx_koff) * 2;
                uint32_t bh[4], bl[4];
                ldsm_x4(bh, base + QK_BHI + boff);
                ldsm_x4(bl, base + QK_BLO + boff);
                #pragma unroll
                for (int h = 0; h < 2; h++)
                    #pragma unroll
                    for (int mi = 0; mi < 2; mi++)
                        mma16816(acc[mi][njp * 2 + h], ahi[mi], &bh[h * 2]);
                #pragma unroll
                for (int h = 0; h < 2; h++)
                    #pragma unroll
                    for (int mi = 0; mi < 2; mi++)
                        mma16816(acc[mi][njp * 2 + h], ahi[mi], &bl[h * 2]);
                #pragma unroll
                for (int h = 0; h < 2; h++)
                    #pragma unroll
                    for (int mi = 0; mi < 2; mi++)
                        mma16816(acc[mi][njp * 2 + h], alo[mi], &bh[h * 2]);
            }
        }
        __syncthreads();
    }

    float* pb = probs + (size_t)b * NS * NS;
    #pragma unroll
    for (int mi = 0; mi < 2; mi++) {
        #pragma unroll
        for (int nj = 0; nj < 8; nj++) {
            int r0 = m0 + warpM + mi * 16 + (lid >> 2);
            int c0 = n0 + warpN + nj * 8 + (lid & 3) * 2;
            *(float2*)&pb[(size_t)r0 * NS + c0]       = make_float2(acc[mi][nj][0], acc[mi][nj][1]);
            *(float2*)&pb[(size_t)(r0 + 8) * NS + c0] = make_float2(acc[mi][nj][2], acc[mi][nj][3]);
        }
    }
}

// ---------------------------------------------------------------------------
// softmax_kernel: warp per row, register resident.
// ---------------------------------------------------------------------------
__global__ __launch_bounds__(256) void softmax_kernel(float* __restrict__ probs)
{
    const int wid = threadIdx.x >> 5, lid = threadIdx.x & 31;
    const int row = blockIdx.x * 8 + wid;
    const size_t base4 = (size_t)row * (NS / 4);

    float4 v[8];
    #pragma unroll
    for (int u = 0; u < 8; u++) v[u] = ((const float4*)probs)[base4 + lid + u * 32];

    float mx = -1e30f;
    #pragma unroll
    for (int u = 0; u < 8; u++) {
        mx = fmaxf(mx, fmaxf(fmaxf(v[u].x, v[u].y), fmaxf(v[u].z, v[u].w)));
    }
    #pragma unroll
    for (int o = 1; o < 32; o <<= 1) mx = fmaxf(mx, __shfl_xor_sync(0xffffffffu, mx, o));

    float sum = 0.f;
    #pragma unroll
    for (int u = 0; u < 8; u++) {
        v[u].x = fast_exp(v[u].x - mx);
        v[u].y = fast_exp(v[u].y - mx);
        v[u].z = fast_exp(v[u].z - mx);
        v[u].w = fast_exp(v[u].w - mx);
        sum += (v[u].x + v[u].y) + (v[u].z + v[u].w);
    }
    #pragma unroll
    for (int o = 1; o < 32; o <<= 1) sum += __shfl_xor_sync(0xffffffffu, sum, o);
    const float inv = 1.f / sum;

    #pragma unroll
    for (int u = 0; u < 8; u++) {
        v[u].x *= inv; v[u].y *= inv; v[u].z *= inv; v[u].w *= inv;
        ((float4*)probs)[base4 + lid + u * 32] = v[u];
        uint2 h, l;
        split2(v[u].x, v[u].y, h.x, l.x);
        split2(v[u].z, v[u].w, h.y, l.y);
        ((uint2*)g_ph)[base4 + lid + u * 32] = h;
        ((uint2*)g_pl)[base4 + lid + u * 32] = l;
    }
}

// ---------------------------------------------------------------------------
// pv_kernel: O = P @ V. grid(8 qtile, 32 b), K=1024, BK=32, 2 CTAs/SM.
// ---------------------------------------------------------------------------
#define PV_PHI 0
#define PV_PLO 10240
#define PV_VHI 20480
#define PV_VLO 29184
#define PV_STAGE 37888
#define PV_SMEM (2 * PV_STAGE)
#define VSTRIDE 136

__global__ __launch_bounds__(256, 2) void pv_kernel(float* __restrict__ o_out)
{
    extern __shared__ char sm[];
    const uint32_t uS = smem_u32(sm);

    const int tid = threadIdx.x;
    const int wid = tid >> 5, lid = tid & 31;
    const int m0 = blockIdx.x * 128;
    const int b  = blockIdx.y;
    const size_t pbase = (size_t)(b * NS + m0) * NS;
    const size_t vbase = (size_t)(b * NS) * ND;

    const int warpM = (wid >> 1) * 32;
    const int warpN = (wid & 1) * 64;
    const int a_row  = lid & 15;
    const int a_koff = (lid >> 4) * 8;
    const int t_krow = (lid & 7) + ((lid >> 3) & 1) * 8;
    const int t_ncol = (lid >> 4) * 8;

    float acc[2][8][4];
    #pragma unroll
    for (int i = 0; i < 2; i++)
        #pragma unroll
        for (int j = 0; j < 8; j++)
            #pragma unroll
            for (int c = 0; c < 4; c++) acc[i][j][c] = 0.f;

    auto issue_stage = [&](int kc, int s) {
        const int k0 = kc * 32;
        const uint32_t base = uS + s * PV_STAGE;
        #pragma unroll
        for (int it = 0; it < 4; it++) {
            int f = tid + it * 256;
            int arr = f >> 9, g = f & 511;
            int row = g >> 2, u = g & 3;
            const __nv_bfloat16* src = (arr ? g_pl : g_ph) + pbase + (size_t)row * NS + k0 + u * 8;
            cp_async16(base + (arr ? PV_PLO : PV_PHI) + (uint32_t)(row * TSTRIDE + u * 8) * 2, src);
        }
        #pragma unroll
        for (int it = 0; it < 4; it++) {
            int f = tid + it * 256;
            int arr = f >> 9, g = f & 511;
            int row = g >> 4, u = g & 15;
            const __nv_bfloat16* src = (arr ? g_vl : g_vh) + vbase + (size_t)(k0 + row) * ND + u * 8;
            cp_async16(base + (arr ? PV_VLO : PV_VHI) + (uint32_t)(row * VSTRIDE + u * 8) * 2, src);
        }
        CP_COMMIT();
    };

    issue_stage(0, 0);

    for (int kc = 0; kc < 32; kc++) {
        if (kc < 31) { issue_stage(kc + 1, (kc + 1) & 1); CP_WAIT(1); }
        else         { CP_WAIT(0); }
        __syncthreads();

        const uint32_t base = uS + (kc & 1) * PV_STAGE;
        #pragma unroll
        for (int ks = 0; ks < 2; ks++) {
            uint32_t ph[2][4], pl[2][4];
            #pragma unroll
            for (int mi = 0; mi < 2; mi++) {
                uint32_t off = ((warpM + mi * 16 + a_row) * TSTRIDE + ks * 16 + a_koff) * 2;
                ldsm_x4(ph[mi], base + PV_PHI + off);
                ldsm_x4(pl[mi], base + PV_PLO + off);
            }
            #pragma unroll
            for (int njp = 0; njp < 4; njp++) {
                uint32_t toff = ((ks * 16 + t_krow) * VSTRIDE + warpN + njp * 16 + t_ncol) * 2;
                uint32_t vh[4], vl[4];
                ldsm_x4_t(vh, base + PV_VHI + toff);
                ldsm_x4_t(vl, base + PV_VLO + toff);
                #pragma unroll
                for (int h = 0; h < 2; h++)
                    #pragma unroll
                    for (int mi = 0; mi < 2; mi++)
                        mma16816(acc[mi][njp * 2 + h], ph[mi], &vh[h * 2]);
                #pragma unroll
                for (int h = 0; h < 2; h++)
                    #pragma unroll
                    for (int mi = 0; mi < 2; mi++)
                        mma16816(acc[mi][njp * 2 + h], ph[mi], &vl[h * 2]);
                #pragma unroll
                for (int h = 0; h < 2; h++)
                    #pragma unroll
                    for (int mi = 0; mi < 2; mi++)
                        mma16816(acc[mi][njp * 2 + h], pl[mi], &vh[h * 2]);
            }
        }
        __syncthreads();
    }

    #pragma unroll
    for (int mi = 0; mi < 2; mi++) {
        #pragma unroll
        for (int nj = 0; nj < 8; nj++) {
            int r0 = m0 + warpM + mi * 16 + (lid >> 2);
            int c0 = warpN + nj * 8 + (lid & 3) * 2;
            *(float2*)&o_out[((size_t)(b * NS) + r0) * ND + c0] =
                make_float2(acc[mi][nj][0], acc[mi][nj][1]);
            *(float2*)&o_out[((size_t)(b * NS) + r0 + 8) * ND + c0] =
                make_float2(acc[mi][nj][2], acc[mi][nj][3]);
        }
    }
}

// ---------------------------------------------------------------------------
extern "C" void kernel_launch(void* const* d_in, const int* in_sizes, int n_in,
                              void* d_out, int out_size)
{
    const float* X  = (const float*)d_in[0];
    const float* Wq = (const float*)d_in[1];
    const float* bq = (const float*)d_in[2];
    const float* Wk = (const float*)d_in[3];
    const float* bk = (const float*)d_in[4];
    const float* Wv = (const float*)d_in[5];
    const float* bv = (const float*)d_in[6];

    float* out   = (float*)d_out;                 // [32,1024,128]
    float* probs = out + (size_t)NB * NS * ND;    // [32,1024,1024]

    cudaFuncSetAttribute(qkv_mma_kernel, cudaFuncAttributeMaxDynamicSharedMemorySize, QK_SMEM);
    cudaFuncSetAttribute(score_kernel, cudaFuncAttributeMaxDynamicSharedMemorySize, QK_SMEM);
    cudaFuncSetAttribute(pv_kernel, cudaFuncAttributeMaxDynamicSharedMemorySize, PV_SMEM);

    convx_kernel<<<8192, 256>>>(X);
    convw_kernel<<<48, 256>>>(Wq, Wk, Wv);
    qkv_mma_kernel<<<dim3(256, 3), 256, QK_SMEM>>>(bq, bk, bv);
    score_kernel<<<dim3(8, 8, 32), 256, QK_SMEM>>>(probs);
    softmax_kernel<<<4096, 256>>>(probs);
    pv_kernel<<<dim3(8, 32), 256, PV_SMEM>>>(out);
}